// round 15
// baseline (speedup 1.0000x reference)
#include <cuda_runtime.h>
#include <cuda_fp16.h>
#include <stdint.h>
#include <math.h>

#define DD   20
#define TPB  128
#define WPB  4               // warps per block
#define NCTA 608             // 152 SMs x 4 CTAs

__device__ double   g_psum[NCTA];
__device__ double   g_pabs[NCTA];
__device__ unsigned g_done = 0;

static __device__ __forceinline__ uint32_t f2tf(float f) {   // exact rna (prologue only)
    uint32_t u; asm("cvt.rna.tf32.f32 %0, %1;" : "=r"(u) : "f"(f)); return u;
}
// rna-to-tf32 via mantissa carry (validated bit-exact vs cvt.rna, R9)
static __device__ __forceinline__ uint32_t rna(float f) {
    return __float_as_uint(f) + 0x1000u;
}
// pack two f32 -> f16x2 (lo = first arg)
static __device__ __forceinline__ uint32_t packh2(float lo, float hi) {
    uint32_t d;
    asm("cvt.rn.f16x2.f32 %0, %1, %2;" : "=r"(d) : "f"(hi), "f"(lo));
    return d;
}
static __device__ __forceinline__ void mma8(float* c, const uint32_t* a, const uint32_t* b) {
    asm volatile("mma.sync.aligned.m16n8k8.row.col.f32.tf32.tf32.f32 "
        "{%0,%1,%2,%3}, {%4,%5,%6,%7}, {%8,%9}, {%0,%1,%2,%3};"
        : "+f"(c[0]), "+f"(c[1]), "+f"(c[2]), "+f"(c[3])
        : "r"(a[0]), "r"(a[1]), "r"(a[2]), "r"(a[3]), "r"(b[0]), "r"(b[1]));
}
static __device__ __forceinline__ void mma16h(float* c, uint32_t a0, uint32_t a1,
                                              uint32_t a2, uint32_t a3,
                                              uint32_t b0, uint32_t b1) {
    asm volatile("mma.sync.aligned.m16n8k16.row.col.f32.f16.f16.f32 "
        "{%0,%1,%2,%3}, {%4,%5,%6,%7}, {%8,%9}, {%0,%1,%2,%3};"
        : "+f"(c[0]), "+f"(c[1]), "+f"(c[2]), "+f"(c[3])
        : "r"(a0), "r"(a1), "r"(a2), "r"(a3), "r"(b0), "r"(b1));
}
static __device__ __forceinline__ void mma8h(float* c, uint32_t a0, uint32_t a1, uint32_t b0) {
    asm volatile("mma.sync.aligned.m16n8k8.row.col.f32.f16.f16.f32 "
        "{%0,%1,%2,%3}, {%4,%5}, {%6}, {%0,%1,%2,%3};"
        : "+f"(c[0]), "+f"(c[1]), "+f"(c[2]), "+f"(c[3])
        : "r"(a0), "r"(a1), "r"(b0));
}
static __device__ __forceinline__ uint32_t s2u(const void* p) {
    uint32_t a;
    asm("{ .reg .u64 t; cvta.to.shared.u64 t, %1; cvt.u32.u64 %0, t; }" : "=r"(a) : "l"(p));
    return a;
}
// fast prefetch: full tile guaranteed in-range, literal offsets
static __device__ __forceinline__ void issue_fast(const char* src, uint32_t dst, int lane) {
    const char* g = src + (uint32_t)lane * 16u;
    uint32_t d = dst + (uint32_t)lane * 16u;
    asm volatile("cp.async.cg.shared.global [%0], [%1], 16;" :: "r"(d),        "l"(g)      : "memory");
    asm volatile("cp.async.cg.shared.global [%0], [%1], 16;" :: "r"(d+512u),  "l"(g+512)  : "memory");
    asm volatile("cp.async.cg.shared.global [%0], [%1], 16;" :: "r"(d+1024u), "l"(g+1024) : "memory");
    asm volatile("cp.async.cg.shared.global [%0], [%1], 16;" :: "r"(d+1536u), "l"(g+1536) : "memory");
    asm volatile("cp.async.cg.shared.global [%0], [%1], 16;" :: "r"(d+2048u), "l"(g+2048) : "memory");
    asm volatile("cp.async.commit_group;" ::: "memory");
}
#define WAIT3() asm volatile("cp.async.wait_group 3;" ::: "memory")
#define WAIT2() asm volatile("cp.async.wait_group 2;" ::: "memory")
#define WAIT1() asm volatile("cp.async.wait_group 1;" ::: "memory")
#define WAIT0() asm volatile("cp.async.wait_group 0;" ::: "memory")

__global__ void __launch_bounds__(TPB, 4)
fused_kernel(const float* __restrict__ X, const float* __restrict__ W,
             const float* __restrict__ bvec, const float* __restrict__ Wi,
             long long nrows_ll, float* __restrict__ out) {
    __shared__ float  sW[400], sWi[400], sM1[400], sc1[DD], sb2[DD];
    __shared__ __align__(16) float sX[WPB][4][32 * DD];  // per-warp X QUAD buffer
    __shared__ double s_rs[WPB], s_ra[WPB];
    __shared__ double fs[TPB], fa[TPB];
    __shared__ int    s_last;

    const int t = threadIdx.x;
    const int wid = t >> 5, lane = t & 31;
    const int qr = lane >> 2, qc = lane & 3;
    const uint32_t nrows = (uint32_t)nrows_ll;

    // ---- prologue: M1 = W^T@Wi, c1 = b@Wi + 1 ----
    for (int i = t; i < 400; i += TPB) { sW[i] = W[i]; sWi[i] = Wi[i]; }
    if (t < DD) sb2[t] = bvec[t];
    __syncthreads();
    for (int e = t; e < 400; e += TPB) {
        int k = e / 20, n = e % 20;
        float a = 0.f;
        #pragma unroll
        for (int j = 0; j < 20; j++) a = fmaf(sW[j*20 + k], sWi[j*20 + n], a);
        sM1[e] = a;
    }
    if (t < DD) {
        float a = 1.f;
        #pragma unroll
        for (int j = 0; j < 20; j++) a = fmaf(sb2[j], sWi[j*20 + t], a);
        sc1[t] = a;
    }
    __syncthreads();

    // ---- stage-1 B fragments (tf32, exact rna) + bias C-inits ----
    uint32_t b1f[3][3][2];
    float    bi1[3][2], bi2[3][2];
    #pragma unroll
    for (int j = 0; j < 3; j++) {
        int k0 = 8*j + qc, k1 = k0 + 4;
        #pragma unroll
        for (int i = 0; i < 3; i++) {
            int n = 8*i + qr;
            float v0 = (k0 < 20 && n < 20) ? sM1[k0*20 + n] : 0.f;
            float v1 = (k1 < 20 && n < 20) ? sM1[k1*20 + n] : 0.f;
            b1f[j][i][0] = f2tf(v0); b1f[j][i][1] = f2tf(v1);
        }
    }
    // ---- stage-2 B fragments (f16): B2[k][n] = W[n][k], n = 8o+qr ----
    uint32_t b2h[3][3];
    #pragma unroll
    for (int o = 0; o < 3; o++) {
        int n = 8*o + qr;
        auto wk = [&](int k) -> float {
            return (k < 20 && n < 20) ? sW[n*20 + k] : 0.f;
        };
        b2h[o][0] = packh2(wk(2*qc),      wk(2*qc + 1));
        b2h[o][1] = packh2(wk(2*qc + 8),  wk(2*qc + 9));
        b2h[o][2] = packh2(wk(2*qc + 16), wk(2*qc + 17));
    }
    #pragma unroll
    for (int i = 0; i < 3; i++) {
        int n0 = 8*i + 2*qc;
        bi1[i][0] = (n0     < 20) ? sc1[n0]     : 0.f;
        bi1[i][1] = (n0 + 1 < 20) ? sc1[n0 + 1] : 0.f;
        bi2[i][0] = (n0     < 20) ? sb2[n0]     : 0.f;
        bi2[i][1] = (n0 + 1 < 20) ? sb2[n0 + 1] : 0.f;
    }

    float aS0 = 0.f, aS1 = 0.f, aA0 = 0.f, aA1 = 0.f;

    const uint32_t ntf = nrows >> 5;                  // full tiles
    const uint32_t gw = (uint32_t)blockIdx.x * WPB + wid;
    const uint32_t nw = (uint32_t)gridDim.x * WPB;
    const char* Xb = (const char*)X;
    const uint32_t xsb[4] = { s2u(&sX[wid][0][0]), s2u(&sX[wid][1][0]),
                              s2u(&sX[wid][2][0]), s2u(&sX[wid][3][0]) };

    // full-tile compute: smem-free stage1 -> relu/cvt -> f16 stage2
    auto do_tile = [&](const float* xs) {
        #pragma unroll
        for (int s = 0; s < 2; s++) {
            const float* q0 = xs + (s*16 + qr) * 20;
            const float* q1 = q0 + 8 * 20;
            uint32_t a[3][4];
            #pragma unroll
            for (int j = 0; j < 2; j++) {
                a[j][0] = rna(q0[8*j + qc]);
                a[j][1] = rna(q1[8*j + qc]);
                a[j][2] = rna(q0[8*j + qc + 4]);
                a[j][3] = rna(q1[8*j + qc + 4]);
            }
            a[2][0] = rna(q0[16 + qc]);
            a[2][1] = rna(q1[16 + qc]);
            a[2][2] = 0u;
            a[2][3] = 0u;

            uint32_t hq[3][2];   // f16x2 A-fragments for stage 2 (C->A reuse)
            #pragma unroll
            for (int i = 0; i < 3; i++) {
                float c[4] = { bi1[i][0], bi1[i][1], bi1[i][0], bi1[i][1] };
                mma8(c, a[0], b1f[0][i]);
                mma8(c, a[1], b1f[1][i]);
                mma8(c, a[2], b1f[2][i]);
                hq[i][0] = packh2(fmaxf(c[0], 0.f), fmaxf(c[1], 0.f));
                hq[i][1] = packh2(fmaxf(c[2], 0.f), fmaxf(c[3], 0.f));
            }
            #pragma unroll
            for (int o = 0; o < 3; o++) {
                float c[4] = { bi2[o][0], bi2[o][1], bi2[o][0], bi2[o][1] };
                mma16h(c, hq[0][0], hq[0][1], hq[1][0], hq[1][1], b2h[o][0], b2h[o][1]);
                mma8h (c, hq[2][0], hq[2][1], b2h[o][2]);
                aS0 += c[0] + c[1]; aA0 += fabsf(c[0]) + fabsf(c[1]);
                aS1 += c[2] + c[3]; aA1 += fabsf(c[2]) + fabsf(c[3]);
            }
        }
    };

    if (gw < ntf) {
        // prime 4 buffers (prefetch distance 3)
        #pragma unroll
        for (int i = 0; i < 4; i++) {
            uint32_t pf = gw + (uint32_t)i * nw; if (pf >= ntf) pf = ntf - 1;
            issue_fast(Xb + (size_t)pf * 2560u, xsb[i], lane);
        }

        uint32_t tl = gw;
        // steady state: 4 tiles per pass, compile-time buffer addresses
        for (; tl + 3*nw < ntf; tl += 4*nw) {
            #pragma unroll
            for (int i = 0; i < 4; i++) {
                WAIT3(); __syncwarp();
                do_tile(&sX[wid][i][0]);
                uint32_t pf = tl + (uint32_t)(i + 4) * nw; if (pf >= ntf) pf = ntf - 1;
                issue_fast(Xb + (size_t)pf * 2560u, xsb[i], lane);
            }
        }
        // tail: 0..3 tiles remain in buffers 0..2
        if (tl < ntf) {
            WAIT3(); __syncwarp();
            do_tile(&sX[wid][0][0]);
            if (tl + nw < ntf) {
                WAIT2(); __syncwarp();
                do_tile(&sX[wid][1][0]);
                if (tl + 2*nw < ntf) {
                    WAIT1(); __syncwarp();
                    do_tile(&sX[wid][2][0]);
                }
            }
        }
    }
    WAIT0();                         // drain speculative prefetches

    // ---- remainder rows (nrows % 32), one warp, plain fp32 (exact) ----
    const uint32_t rem = nrows & 31u;
    if (rem && blockIdx.x == 0 && wid == 0 && (uint32_t)lane < rem) {
        uint32_t r = (nrows & ~31u) + (uint32_t)lane;
        const float* xr = X + (size_t)r * DD;
        float hv[DD];
        #pragma unroll
        for (int m = 0; m < DD; m++) {
            float a = sc1[m];
            #pragma unroll
            for (int k = 0; k < DD; k++) a = fmaf(xr[k], sM1[k*20 + m], a);
            hv[m] = fmaxf(a, 0.f);
        }
        #pragma unroll
        for (int n = 0; n < DD; n++) {
            float a = sb2[n];
            #pragma unroll
            for (int m = 0; m < DD; m++) a = fmaf(hv[m], sW[n*20 + m], a);
            aS0 += a; aA0 += fabsf(a);
        }
    }

    // ---- CTA reduce ----
    float accS = aS0 + aS1, accA = aA0 + aA1;
    #pragma unroll
    for (int o = 16; o > 0; o >>= 1) {
        accS += __shfl_down_sync(0xFFFFFFFFu, accS, o);
        accA += __shfl_down_sync(0xFFFFFFFFu, accA, o);
    }
    if (lane == 0) { s_rs[wid] = (double)accS; s_ra[wid] = (double)accA; }
    __syncthreads();

    if (t == 0) {
        double S = s_rs[0] + s_rs[1] + s_rs[2] + s_rs[3];
        double A = s_ra[0] + s_ra[1] + s_ra[2] + s_ra[3];
        g_psum[blockIdx.x] = S;
        g_pabs[blockIdx.x] = A;
        __threadfence();
        unsigned v = atomicAdd(&g_done, 1u);
        s_last = (v == gridDim.x - 1) ? 1 : 0;
    }
    __syncthreads();

    // ---- last CTA: global reduce + exact halving count + write scalar ----
    if (s_last) {
        __threadfence();
        double S = 0.0, A = 0.0;
        for (int i = t; i < (int)gridDim.x; i += TPB) { S += g_psum[i]; A += g_pabs[i]; }
        fs[t] = S; fa[t] = A;
        __syncthreads();
        for (int o = TPB/2; o > 0; o >>= 1) {
            if (t < o) { fs[t] += fs[t + o]; fa[t] += fa[t + o]; }
            __syncthreads();
        }
        if (t == 0) {
            float s = (float)fa[0];
            int k = 0;
            while (s > 1.0f && k < 300) { s *= 0.5f; k++; }
            out[0] = (float)ldexp(fs[0], -k);   // sum(h) * 2^-k (exact scale)
            __threadfence();
            g_done = 0;                          // reset for next graph replay
        }
    }
}

// ---------------- launch ----------------
extern "C" void kernel_launch(void* const* d_in, const int* in_sizes, int n_in,
                              void* d_out, int out_size) {
    const float* X  = (const float*)d_in[0];
    const float* W  = (const float*)d_in[1];
    const float* b  = (const float*)d_in[2];
    const float* Wi = (const float*)d_in[3];

    long long nrows = (long long)in_sizes[0] / DD;

    fused_kernel<<<NCTA, TPB>>>(X, W, b, Wi, nrows, (float*)d_out);
}

// round 16
// speedup vs baseline: 1.3597x; 1.3597x over previous
#include <cuda_runtime.h>
#include <cuda_fp16.h>
#include <stdint.h>
#include <math.h>

#define DD   20
#define TPB  128
#define WPB  4               // warps per block
#define NCTA 608             // 152 SMs x 4 CTAs

__device__ double   g_psum[NCTA];
__device__ double   g_pabs[NCTA];
__device__ unsigned g_done = 0;

// pack two f32 -> f16x2 (lo = first arg)
static __device__ __forceinline__ uint32_t packh2(float lo, float hi) {
    uint32_t d;
    asm("cvt.rn.f16x2.f32 %0, %1, %2;" : "=r"(d) : "f"(hi), "f"(lo));
    return d;
}
static __device__ __forceinline__ void mma16h(float* c, uint32_t a0, uint32_t a1,
                                              uint32_t a2, uint32_t a3,
                                              uint32_t b0, uint32_t b1) {
    asm volatile("mma.sync.aligned.m16n8k16.row.col.f32.f16.f16.f32 "
        "{%0,%1,%2,%3}, {%4,%5,%6,%7}, {%8,%9}, {%0,%1,%2,%3};"
        : "+f"(c[0]), "+f"(c[1]), "+f"(c[2]), "+f"(c[3])
        : "r"(a0), "r"(a1), "r"(a2), "r"(a3), "r"(b0), "r"(b1));
}
static __device__ __forceinline__ void mma8h(float* c, uint32_t a0, uint32_t a1, uint32_t b0) {
    asm volatile("mma.sync.aligned.m16n8k8.row.col.f32.f16.f16.f32 "
        "{%0,%1,%2,%3}, {%4,%5}, {%6}, {%0,%1,%2,%3};"
        : "+f"(c[0]), "+f"(c[1]), "+f"(c[2]), "+f"(c[3])
        : "r"(a0), "r"(a1), "r"(b0));
}
static __device__ __forceinline__ uint32_t s2u(const void* p) {
    uint32_t a;
    asm("{ .reg .u64 t; cvta.to.shared.u64 t, %1; cvt.u32.u64 %0, t; }" : "=r"(a) : "l"(p));
    return a;
}
// fast prefetch: full tile guaranteed in-range, literal offsets
static __device__ __forceinline__ void issue_fast(const char* src, uint32_t dst, int lane) {
    const char* g = src + (uint32_t)lane * 16u;
    uint32_t d = dst + (uint32_t)lane * 16u;
    asm volatile("cp.async.cg.shared.global [%0], [%1], 16;" :: "r"(d),        "l"(g)      : "memory");
    asm volatile("cp.async.cg.shared.global [%0], [%1], 16;" :: "r"(d+512u),  "l"(g+512)  : "memory");
    asm volatile("cp.async.cg.shared.global [%0], [%1], 16;" :: "r"(d+1024u), "l"(g+1024) : "memory");
    asm volatile("cp.async.cg.shared.global [%0], [%1], 16;" :: "r"(d+1536u), "l"(g+1536) : "memory");
    asm volatile("cp.async.cg.shared.global [%0], [%1], 16;" :: "r"(d+2048u), "l"(g+2048) : "memory");
    asm volatile("cp.async.commit_group;" ::: "memory");
}
#define WAIT1() asm volatile("cp.async.wait_group 1;" ::: "memory")
#define WAIT0() asm volatile("cp.async.wait_group 0;" ::: "memory")

__global__ void __launch_bounds__(TPB, 4)
fused_kernel(const float* __restrict__ X, const float* __restrict__ W,
             const float* __restrict__ bvec, const float* __restrict__ Wi,
             long long nrows_ll, float* __restrict__ out) {
    __shared__ float  sW[400], sWi[400], sM1[400], sc1[DD], sb2[DD];
    __shared__ __align__(16) float sX[WPB][2][32 * DD];  // per-warp X double buffer
    __shared__ double s_rs[WPB], s_ra[WPB];
    __shared__ double fs[TPB], fa[TPB];
    __shared__ int    s_last;

    const int t = threadIdx.x;
    const int wid = t >> 5, lane = t & 31;
    const int qr = lane >> 2, qc = lane & 3;
    const uint32_t nrows = (uint32_t)nrows_ll;

    // ---- prologue: M1 = W^T@Wi, c1 = b@Wi + 1 ----
    for (int i = t; i < 400; i += TPB) { sW[i] = W[i]; sWi[i] = Wi[i]; }
    if (t < DD) sb2[t] = bvec[t];
    __syncthreads();
    for (int e = t; e < 400; e += TPB) {
        int k = e / 20, n = e % 20;
        float a = 0.f;
        #pragma unroll
        for (int j = 0; j < 20; j++) a = fmaf(sW[j*20 + k], sWi[j*20 + n], a);
        sM1[e] = a;
    }
    if (t < DD) {
        float a = 1.f;
        #pragma unroll
        for (int j = 0; j < 20; j++) a = fmaf(sb2[j], sWi[j*20 + t], a);
        sc1[t] = a;
    }
    __syncthreads();

    // ---- stage-1 B fragments (f16): B1[k][n] = M1[k][n], n = 8i+qr ----
    // per i: [0],[1] = m16n8k16 b0/b1 (k = 2qc,2qc+1 / 2qc+8,2qc+9)
    //        [2]     = m16n8k8  b0    (k = 16+2qc, 17+2qc)
    uint32_t b1h[3][3];
    #pragma unroll
    for (int i = 0; i < 3; i++) {
        int n = 8*i + qr;
        auto mk = [&](int k) -> float {
            return (k < 20 && n < 20) ? sM1[k*20 + n] : 0.f;
        };
        b1h[i][0] = packh2(mk(2*qc),      mk(2*qc + 1));
        b1h[i][1] = packh2(mk(2*qc + 8),  mk(2*qc + 9));
        b1h[i][2] = packh2(mk(2*qc + 16), mk(2*qc + 17));
    }
    // ---- stage-2 B fragments (f16): B2[k][n] = W[n][k], n = 8o+qr ----
    uint32_t b2h[3][3];
    #pragma unroll
    for (int o = 0; o < 3; o++) {
        int n = 8*o + qr;
        auto wk = [&](int k) -> float {
            return (k < 20 && n < 20) ? sW[n*20 + k] : 0.f;
        };
        b2h[o][0] = packh2(wk(2*qc),      wk(2*qc + 1));
        b2h[o][1] = packh2(wk(2*qc + 8),  wk(2*qc + 9));
        b2h[o][2] = packh2(wk(2*qc + 16), wk(2*qc + 17));
    }
    float bi1[3][2], bi2[3][2];
    #pragma unroll
    for (int i = 0; i < 3; i++) {
        int n0 = 8*i + 2*qc;
        bi1[i][0] = (n0     < 20) ? sc1[n0]     : 0.f;
        bi1[i][1] = (n0 + 1 < 20) ? sc1[n0 + 1] : 0.f;
        bi2[i][0] = (n0     < 20) ? sb2[n0]     : 0.f;
        bi2[i][1] = (n0 + 1 < 20) ? sb2[n0 + 1] : 0.f;
    }

    float aS0 = 0.f, aS1 = 0.f, aA0 = 0.f, aA1 = 0.f;

    const uint32_t ntf = nrows >> 5;                  // full tiles
    const uint32_t gw = (uint32_t)blockIdx.x * WPB + wid;
    const uint32_t nw = (uint32_t)gridDim.x * WPB;
    const char* Xb = (const char*)X;
    const uint32_t xs0 = s2u(&sX[wid][0][0]);
    const uint32_t xs1 = s2u(&sX[wid][1][0]);

    const bool k8ok = (qc < 2);   // k = 16+2qc < 20 only for qc in {0,1}

    // full-tile compute: f16 stage1 -> relu/pack -> f16 stage2, all in regs
    auto do_tile = [&](const float* xs) {
        #pragma unroll
        for (int s = 0; s < 2; s++) {
            const float* q0 = xs + (s*16 + qr) * 20;
            const float* q1 = q0 + 8 * 20;

            // ---- f16 A fragments: LDS.64 float2 + 1 cvt each ----
            uint32_t ax[6];
            float2 v;
            v = *(const float2*)(q0 + 2*qc);       ax[0] = packh2(v.x, v.y);
            v = *(const float2*)(q1 + 2*qc);       ax[1] = packh2(v.x, v.y);
            v = *(const float2*)(q0 + 2*qc + 8);   ax[2] = packh2(v.x, v.y);
            v = *(const float2*)(q1 + 2*qc + 8);   ax[3] = packh2(v.x, v.y);
            if (k8ok) {
                v = *(const float2*)(q0 + 2*qc + 16); ax[4] = packh2(v.x, v.y);
                v = *(const float2*)(q1 + 2*qc + 16); ax[5] = packh2(v.x, v.y);
            } else { ax[4] = 0u; ax[5] = 0u; }

            // ---- stage 1 (f16): h = relu(X @ M1 + c1) ----
            uint32_t hq[3][2];   // f16x2 A-fragments for stage 2 (C->A reuse)
            #pragma unroll
            for (int i = 0; i < 3; i++) {
                float c[4] = { bi1[i][0], bi1[i][1], bi1[i][0], bi1[i][1] };
                mma16h(c, ax[0], ax[1], ax[2], ax[3], b1h[i][0], b1h[i][1]);
                mma8h (c, ax[4], ax[5], b1h[i][2]);
                hq[i][0] = packh2(fmaxf(c[0], 0.f), fmaxf(c[1], 0.f));
                hq[i][1] = packh2(fmaxf(c[2], 0.f), fmaxf(c[3], 0.f));
            }
            // ---- stage 2 (f16): h3 = h @ W^T + b ----
            #pragma unroll
            for (int o = 0; o < 3; o++) {
                float c[4] = { bi2[o][0], bi2[o][1], bi2[o][0], bi2[o][1] };
                mma16h(c, hq[0][0], hq[0][1], hq[1][0], hq[1][1], b2h[o][0], b2h[o][1]);
                mma8h (c, hq[2][0], hq[2][1], b2h[o][2]);
                aS0 += c[0] + c[1]; aA0 += fabsf(c[0]) + fabsf(c[1]);
                aS1 += c[2] + c[3]; aA1 += fabsf(c[2]) + fabsf(c[3]);
            }
        }
    };

    if (gw < ntf) {
        uint32_t pf1 = gw + nw; if (pf1 >= ntf) pf1 = ntf - 1;
        issue_fast(Xb + (size_t)gw  * 2560u, xs0, lane);
        issue_fast(Xb + (size_t)pf1 * 2560u, xs1, lane);

        uint32_t tl = gw;
        for (; tl + nw < ntf; tl += 2*nw) {
            WAIT1(); __syncwarp();
            do_tile(&sX[wid][0][0]);
            uint32_t pf = tl + 2*nw; if (pf >= ntf) pf = ntf - 1;
            issue_fast(Xb + (size_t)pf * 2560u, xs0, lane);

            WAIT1(); __syncwarp();
            do_tile(&sX[wid][1][0]);
            pf = tl + 3*nw; if (pf >= ntf) pf = ntf - 1;
            issue_fast(Xb + (size_t)pf * 2560u, xs1, lane);
        }
        if (tl < ntf) {
            WAIT1(); __syncwarp();
            do_tile(&sX[wid][0][0]);
        }
    }
    WAIT0();                         // drain speculative prefetches

    // ---- remainder rows (nrows % 32), one warp, plain fp32 (exact) ----
    const uint32_t rem = nrows & 31u;
    if (rem && blockIdx.x == 0 && wid == 0 && (uint32_t)lane < rem) {
        uint32_t r = (nrows & ~31u) + (uint32_t)lane;
        const float* xr = X + (size_t)r * DD;
        float hv[DD];
        #pragma unroll
        for (int m = 0; m < DD; m++) {
            float a = sc1[m];
            #pragma unroll
            for (int k = 0; k < DD; k++) a = fmaf(xr[k], sM1[k*20 + m], a);
            hv[m] = fmaxf(a, 0.f);
        }
        #pragma unroll
        for (int n = 0; n < DD; n++) {
            float a = sb2[n];
            #pragma unroll
            for (int m = 0; m < DD; m++) a = fmaf(hv[m], sW[n*20 + m], a);
            aS0 += a; aA0 += fabsf(a);
        }
    }

    // ---- CTA reduce ----
    float accS = aS0 + aS1, accA = aA0 + aA1;
    #pragma unroll
    for (int o = 16; o > 0; o >>= 1) {
        accS += __shfl_down_sync(0xFFFFFFFFu, accS, o);
        accA += __shfl_down_sync(0xFFFFFFFFu, accA, o);
    }
    if (lane == 0) { s_rs[wid] = (double)accS; s_ra[wid] = (double)accA; }
    __syncthreads();

    if (t == 0) {
        double S = s_rs[0] + s_rs[1] + s_rs[2] + s_rs[3];
        double A = s_ra[0] + s_ra[1] + s_ra[2] + s_ra[3];
        g_psum[blockIdx.x] = S;
        g_pabs[blockIdx.x] = A;
        __threadfence();
        unsigned v = atomicAdd(&g_done, 1u);
        s_last = (v == gridDim.x - 1) ? 1 : 0;
    }
    __syncthreads();

    // ---- last CTA: global reduce + exact halving count + write scalar ----
    if (s_last) {
        __threadfence();
        double S = 0.0, A = 0.0;
        for (int i = t; i < (int)gridDim.x; i += TPB) { S += g_psum[i]; A += g_pabs[i]; }
        fs[t] = S; fa[t] = A;
        __syncthreads();
        for (int o = TPB/2; o > 0; o >>= 1) {
            if (t < o) { fs[t] += fs[t + o]; fa[t] += fa[t + o]; }
            __syncthreads();
        }
        if (t == 0) {
            float s = (float)fa[0];
            int k = 0;
            while (s > 1.0f && k < 300) { s *= 0.5f; k++; }
            out[0] = (float)ldexp(fs[0], -k);   // sum(h) * 2^-k (exact scale)
            __threadfence();
            g_done = 0;                          // reset for next graph replay
        }
    }
}

// ---------------- launch ----------------
extern "C" void kernel_launch(void* const* d_in, const int* in_sizes, int n_in,
                              void* d_out, int out_size) {
    const float* X  = (const float*)d_in[0];
    const float* W  = (const float*)d_in[1];
    const float* b  = (const float*)d_in[2];
    const float* Wi = (const float*)d_in[3];

    long long nrows = (long long)in_sizes[0] / DD;

    fused_kernel<<<NCTA, TPB>>>(X, W, b, Wi, nrows, (float*)d_out);
}